// round 17
// baseline (speedup 1.0000x reference)
#include <cuda_runtime.h>
#include <cuda_bf16.h>
#include <cstdint>

// ---------------- problem constants ----------------
#define B_BATCH 64
#define N_NODES 1024
#define S_LOC   12
#define HID     64
#define PAT     32
#define M_GLB   64
#define S_GLB   6
#define M_LOC   64
#define D_EMB   16
#define KDIM    768           // S_LOC * HID
#define CDIM    128           // M_LOC + M_GLB
#define ROWS    65536         // B_BATCH * N_NODES
#define NCHUNK  12            // K chunks of 64

// tcgen05 is arch-SPECIFIC: only emit its PTX in the sm_103a/sm_100a pass.
#if defined(__CUDA_ARCH_FEAT_SM103_ALL) || defined(__CUDA_ARCH_FEAT_SM100_ALL) || \
    (defined(__CUDA_ARCH_SPECIFIC__) && (__CUDA_ARCH_SPECIFIC__ == 1030 || __CUDA_ARCH_SPECIFIC__ == 1000))
#define HAS_TCGEN05 1
#else
#define HAS_TCGEN05 0
#endif

// ---------------- static device scratch ----------------
__device__ __align__(16) float g_A[KDIM * CDIM];           // only used by generic fallback
__device__ __align__(16) float g_bias[CDIM];
__device__ __align__(16) float g_Lm[M_LOC * PAT];
__device__ __align__(16) float g_Gm[M_GLB * PAT];
__device__ __align__(16) float g_nw[N_NODES * 64 * HID];   // [1024][64][64]
__device__ __align__(16) float g_sim[(size_t)ROWS * CDIM]; // logits [65536][128]
// pre-swizzled bf16 B operand (hi/lo), [chunk][128 n-rows][128 bytes]
__device__ __align__(16) unsigned char g_Bhi[NCHUNK * 128 * 128];
__device__ __align__(16) unsigned char g_Blo[NCHUNK * 128 * 128];

// ---------------- helpers legal on all targets ----------------
__device__ __forceinline__ uint32_t su32(const void* p) {
    uint32_t a;
    asm("{ .reg .u64 t; cvta.to.shared.u64 t, %1; cvt.u32.u64 %0, t; }" : "=r"(a) : "l"(p));
    return a;
}
__device__ __forceinline__ uint32_t bf16pack(float x0, float x1) {
    uint32_t r;
    asm("cvt.rn.bf16x2.f32 %0, %1, %2;" : "=r"(r) : "f"(x1), "f"(x0));
    return r;
}
__device__ __forceinline__ void bf16split(float x0, float x1, uint32_t& hi, uint32_t& lo) {
    hi = bf16pack(x0, x1);
    float h0 = __uint_as_float(hi << 16);
    float h1 = __uint_as_float(hi & 0xffff0000u);
    lo = bf16pack(x0 - h0, x1 - h1);
}
__device__ __forceinline__ void cp16(uint32_t saddr, const void* gaddr) {
    asm volatile("cp.async.cg.shared.global [%0], [%1], 16;" :: "r"(saddr), "l"(gaddr) : "memory");
}

#if HAS_TCGEN05
__device__ __forceinline__ uint32_t elect1() {
    uint32_t r;
    asm volatile("{ .reg .pred p; elect.sync _|p, 0xFFFFFFFF; selp.b32 %0, 1, 0, p; }" : "=r"(r));
    return r;
}
__device__ __forceinline__ uint64_t mkdesc(uint32_t saddr) {
    // SW128 K-major: layout=2, version=1, SBO=64, LBO=1
    return 0x4000404000010000ULL | ((uint64_t)(saddr >> 4) & 0x3FFF);
}
__device__ __forceinline__ void mma_f16_ss(uint32_t d, uint64_t ad, uint64_t bd,
                                           uint32_t idesc, uint32_t en) {
    asm volatile(
        "{\n\t.reg .pred p;\n\tsetp.ne.u32 p, %4, 0;\n\t"
        "tcgen05.mma.cta_group::1.kind::f16 [%0], %1, %2, %3, {%5, %5, %5, %5}, p;\n\t}"
        :: "r"(d), "l"(ad), "l"(bd), "r"(idesc), "r"(en), "r"(0u) : "memory");
}
#define MBAR_INIT(a, n) asm volatile("mbarrier.init.shared.b64 [%0], %1;" :: "r"(a), "r"(n) : "memory")
#define MBAR_WAITP(addr, par) do {                                                      \
    uint32_t _m = (addr), _p = (par), _d;                                               \
    asm volatile("{\n\t.reg .pred p;\n\t"                                               \
        "mbarrier.try_wait.parity.acquire.cta.shared::cta.b64 p, [%1], %2;\n\t"         \
        "selp.b32 %0, 1, 0, p;\n\t}" : "=r"(_d) : "r"(_m), "r"(_p) : "memory");         \
    if (!_d) {                                                                          \
        asm volatile("{\n\t.reg .pred P1;\n\tWL_%=:\n\t"                                \
            "mbarrier.try_wait.parity.acquire.cta.shared::cta.b64 P1, [%0], %1, 0x989680;\n\t" \
            "@P1 bra.uni WD_%=;\n\tbra.uni WL_%=;\n\tWD_%=:\n\t}"                       \
            :: "r"(_m), "r"(_p) : "memory");                                            \
    }                                                                                   \
} while (0)
#define TC_COMMIT(a) asm volatile("tcgen05.commit.cta_group::1.mbarrier::arrive::one.shared::cluster.b64 [%0];" :: "r"(a) : "memory")
#define TC_WAITLD()  asm volatile("tcgen05.wait::ld.sync.aligned;" ::: "memory")
#define LDTM32(r, a) asm volatile(                                                      \
    "tcgen05.ld.sync.aligned.32x32b.x32.b32 "                                           \
    "{%0, %1, %2, %3, %4, %5, %6, %7, %8, %9, %10, %11, %12, %13, %14, %15, "           \
    " %16, %17, %18, %19, %20, %21, %22, %23, %24, %25, %26, %27, %28, %29, %30, %31}, [%32];" \
    : "=r"((r)[0]), "=r"((r)[1]), "=r"((r)[2]), "=r"((r)[3]),                           \
      "=r"((r)[4]), "=r"((r)[5]), "=r"((r)[6]), "=r"((r)[7]),                           \
      "=r"((r)[8]), "=r"((r)[9]), "=r"((r)[10]), "=r"((r)[11]),                         \
      "=r"((r)[12]), "=r"((r)[13]), "=r"((r)[14]), "=r"((r)[15]),                       \
      "=r"((r)[16]), "=r"((r)[17]), "=r"((r)[18]), "=r"((r)[19]),                       \
      "=r"((r)[20]), "=r"((r)[21]), "=r"((r)[22]), "=r"((r)[23]),                       \
      "=r"((r)[24]), "=r"((r)[25]), "=r"((r)[26]), "=r"((r)[27]),                       \
      "=r"((r)[28]), "=r"((r)[29]), "=r"((r)[30]), "=r"((r)[31])                        \
    : "r"(a))
// idesc: fp32 accum, bf16 x bf16, M=128, N=128, K-major both
#define IDESC_BF16 0x8200490u
#endif  // HAS_TCGEN05

// ================= P0: pFold — folded-weight split/swizzle (12 blocks) =================
__global__ __launch_bounds__(256) void pFold_kernel(const float* __restrict__ G,
                                                    const float* __restrict__ L,
                                                    const float* __restrict__ Wq) {
    __shared__ float sWq[64][36];
    __shared__ float sBl[64][36];
    __shared__ float sBg[64][36];
    int ci = blockIdx.x, tid = threadIdx.x;
    for (int i = tid; i < 64 * 32; i += 256) sWq[i >> 5][i & 31] = Wq[i];
    for (int i = tid; i < 2048; i += 256) {
        int c = i >> 5, p = i & 31;
        sBl[c][p] = L[c * (S_LOC * PAT) + ci * PAT + p];
        sBg[c][p] = G[c * (S_GLB * PAT) + (ci >> 1) * PAT + p];
    }
    __syncthreads();
    #pragma unroll
    for (int it = 0; it < 4; it++) {
        int task = it * 256 + tid;
        int kq = (task >> 7) & 7;
        int n  = task & 127;
        const float* bank = (n < 64) ? &sBl[n][0] : &sBg[n - 64][0];
        float scale = (n < 64) ? 1.0f : 0.5f;
        uint32_t hi[4], lo[4];
        #pragma unroll
        for (int p2 = 0; p2 < 4; p2++) {
            int h0 = kq * 8 + 2 * p2;
            float x0 = 0.f, x1 = 0.f;
            #pragma unroll
            for (int p = 0; p < 32; p++) {
                float bp = bank[p];
                x0 += sWq[h0][p] * bp;
                x1 += sWq[h0 + 1][p] * bp;
            }
            bf16split(x0 * scale, x1 * scale, hi[p2], lo[p2]);
        }
        int off = n * 128 + kq * 16;
        int swo = off ^ ((off >> 3) & 0x70);
        *(uint4*)(g_Bhi + ci * 16384 + swo) = make_uint4(hi[0], hi[1], hi[2], hi[3]);
        *(uint4*)(g_Blo + ci * 16384 + swo) = make_uint4(lo[0], lo[1], lo[2], lo[3]);
    }
}

// ================= P1: pAux — bias + bank means =================
__global__ void pAux_kernel(const float* __restrict__ G, const float* __restrict__ L,
                            const float* __restrict__ bq) {
    if (blockIdx.x == 0) {
        int c = threadIdx.x;
        if (c >= 128) return;
        float v = 0.f;
        if (c < 64) {
            for (int s = 0; s < S_LOC; s++)
                #pragma unroll
                for (int p = 0; p < PAT; p++) v += bq[p] * L[c * (S_LOC * PAT) + s * PAT + p];
        } else {
            for (int s = 0; s < S_GLB; s++)
                #pragma unroll
                for (int p = 0; p < PAT; p++) v += bq[p] * G[(c - 64) * (S_GLB * PAT) + s * PAT + p];
        }
        g_bias[c] = v;
    } else {
        int idx = (blockIdx.x - 1) * 256 + threadIdx.x;
        if (idx >= 2048) return;
        int m = idx >> 5, p = idx & 31;
        float lm = 0.f, gm = 0.f;
        for (int s = 0; s < S_LOC; s++) lm += L[m * (S_LOC * PAT) + s * PAT + p];
        for (int s = 0; s < S_GLB; s++) gm += G[m * (S_GLB * PAT) + s * PAT + p];
        g_Lm[idx] = lm * (1.f / 12.f);
        g_Gm[idx] = gm * (1.f / 6.f);
    }
}

// ================= P2: node_w = emb @ pool (4 nodes/block, float4 ILP) =================
__global__ __launch_bounds__(256) void pNw_kernel(const float* __restrict__ emb,
                                                  const float* __restrict__ pool) {
    __shared__ float se[4][16];
    int n0 = blockIdx.x << 2, tid = threadIdx.x;
    if (tid < 64) se[tid >> 4][tid & 15] = emb[(n0 + (tid >> 4)) * D_EMB + (tid & 15)];
    __syncthreads();
    float e0[16], e1[16], e2[16], e3[16];
    #pragma unroll
    for (int d = 0; d < 16; d++) {
        e0[d] = se[0][d]; e1[d] = se[1][d]; e2[d] = se[2][d]; e3[d] = se[3][d];
    }
    const float4* p4 = (const float4*)pool;
    #pragma unroll
    for (int j = 0; j < 4; j++) {
        int o = j * 256 + tid;
        float4 a0 = {0, 0, 0, 0}, a1 = a0, a2 = a0, a3 = a0;
        #pragma unroll
        for (int d = 0; d < 16; d++) {
            float4 pv = p4[d * 1024 + o];
            a0.x += e0[d] * pv.x; a0.y += e0[d] * pv.y; a0.z += e0[d] * pv.z; a0.w += e0[d] * pv.w;
            a1.x += e1[d] * pv.x; a1.y += e1[d] * pv.y; a1.z += e1[d] * pv.z; a1.w += e1[d] * pv.w;
            a2.x += e2[d] * pv.x; a2.y += e2[d] * pv.y; a2.z += e2[d] * pv.z; a2.w += e2[d] * pv.w;
            a3.x += e3[d] * pv.x; a3.y += e3[d] * pv.y; a3.z += e3[d] * pv.z; a3.w += e3[d] * pv.w;
        }
        float4* nw4 = (float4*)g_nw;
        nw4[(size_t)(n0 + 0) * 1024 + o] = a0;
        nw4[(size_t)(n0 + 1) * 1024 + o] = a1;
        nw4[(size_t)(n0 + 2) * 1024 + o] = a2;
        nw4[(size_t)(n0 + 3) * 1024 + o] = a3;
    }
}

// ================= K1: tcgen05 bf16x3 GEMM, register-pipelined H loads =================
// Single-stage ring (66.5 KB -> 3 CTAs/SM); chunk c+1's H LDGs issued right after
// chunk c's MMAs so LDG latency overlaps MMA execution + completion wait.
#define K1_SMEM (1024 + 65536)
__global__ __launch_bounds__(256, 3) void k1_tc(const float* __restrict__ H) {
#if HAS_TCGEN05
    extern __shared__ __align__(1024) char smem[];
    const int tid = threadIdx.x, w = tid >> 5, lane = tid & 31;
    const int row0 = blockIdx.x << 7;
    uint32_t sb = su32(smem);

    if (w == 0) {
        asm volatile("tcgen05.alloc.cta_group::1.sync.aligned.shared::cta.b32 [%0], %1;"
                     :: "r"(sb), "r"(128u) : "memory");
        asm volatile("tcgen05.relinquish_alloc_permit.cta_group::1.sync.aligned;");
    }
    if (tid == 0) MBAR_INIT(sb + 16, 1);
    float* sbias = (float*)(smem + 64);
    if (tid < 128) sbias[tid] = g_bias[tid];
    __syncthreads();
    uint32_t tmem;
    asm("ld.shared.b32 %0, [%1];" : "=r"(tmem) : "r"(sb));

    char* buf = smem + 1024;
    const uint32_t bufb = sb + 1024;

    // per-thread H task geometry (fixed across chunks)
    const int r_t  = tid >> 3;            // rows 0..31 handled by it-stride below
    const int kq_t = tid & 7;

    float4 pre[8];
    // prefetch chunk 0
    #pragma unroll
    for (int it = 0; it < 4; it++) {
        const float* hp = H + (size_t)(row0 + r_t + it * 32) * KDIM + kq_t * 8;
        pre[2 * it]     = *(const float4*)hp;
        pre[2 * it + 1] = *(const float4*)(hp + 4);
    }

    for (int c = 0; c < NCHUNK; c++) {
        if (c > 0) MBAR_WAITP(sb + 16, (uint32_t)((c - 1) & 1));

        // B via cp.async (pre-swizzled, L2-hot)
        {
            const char* bh = (const char*)g_Bhi + c * 16384 + tid * 16;
            const char* bl = (const char*)g_Blo + c * 16384 + tid * 16;
            uint32_t dh = bufb + 32768 + tid * 16;
            uint32_t dl = bufb + 49152 + tid * 16;
            #pragma unroll
            for (int i = 0; i < 4; i++) {
                cp16(dh + i * 4096, bh + i * 4096);
                cp16(dl + i * 4096, bl + i * 4096);
            }
            asm volatile("cp.async.commit_group;" ::: "memory");
        }
        // A: split prefetched registers, swizzled STS (no LDG exposure here)
        #pragma unroll
        for (int it = 0; it < 4; it++) {
            int r = r_t + it * 32;
            uint32_t hi[4], lo[4];
            bf16split(pre[2 * it].x,     pre[2 * it].y,     hi[0], lo[0]);
            bf16split(pre[2 * it].z,     pre[2 * it].w,     hi[1], lo[1]);
            bf16split(pre[2 * it + 1].x, pre[2 * it + 1].y, hi[2], lo[2]);
            bf16split(pre[2 * it + 1].z, pre[2 * it + 1].w, hi[3], lo[3]);
            int off = r * 128 + kq_t * 16;
            int swo = off ^ ((off >> 3) & 0x70);
            *(uint4*)(buf + swo)         = make_uint4(hi[0], hi[1], hi[2], hi[3]);
            *(uint4*)(buf + 16384 + swo) = make_uint4(lo[0], lo[1], lo[2], lo[3]);
        }
        asm volatile("cp.async.wait_group 0;" ::: "memory");
        asm volatile("fence.proxy.async.shared::cta;" ::: "memory");
        __syncthreads();

        if (w == 0 && elect1()) {
            uint64_t ah = mkdesc(bufb);
            uint64_t al = mkdesc(bufb + 16384);
            uint64_t bh = mkdesc(bufb + 32768);
            uint64_t bl = mkdesc(bufb + 49152);
            #pragma unroll
            for (int ks = 0; ks < 4; ks++) {
                uint32_t en0 = (c == 0 && ks == 0) ? 0u : 1u;
                mma_f16_ss(tmem, ah + 2 * ks, bh + 2 * ks, IDESC_BF16, en0);
                mma_f16_ss(tmem, ah + 2 * ks, bl + 2 * ks, IDESC_BF16, 1u);
                mma_f16_ss(tmem, al + 2 * ks, bh + 2 * ks, IDESC_BF16, 1u);
            }
            TC_COMMIT(sb + 16);
        }

        // prefetch next chunk's H while MMAs run / complete
        if (c + 1 < NCHUNK) {
            #pragma unroll
            for (int it = 0; it < 4; it++) {
                const float* hp = H + (size_t)(row0 + r_t + it * 32) * KDIM
                                    + (c + 1) * 64 + kq_t * 8;
                pre[2 * it]     = *(const float4*)hp;
                pre[2 * it + 1] = *(const float4*)(hp + 4);
            }
        }
    }

    // 12th commit -> parity 11&1 = 1
    MBAR_WAITP(sb + 16, 1u);
    asm volatile("tcgen05.fence::after_thread_sync;" ::: "memory");

    if (w < 4) {
        #pragma unroll
        for (int base = 0; base < 128; base += 32) {
            uint32_t dr[32];
            LDTM32(dr, tmem + base);
            TC_WAITLD();
            float* op = g_sim + (size_t)(row0 + w * 32 + lane) * CDIM + base;
            #pragma unroll
            for (int j = 0; j < 32; j += 4) {
                float4 o;
                o.x = __uint_as_float(dr[j + 0]) + sbias[base + j + 0];
                o.y = __uint_as_float(dr[j + 1]) + sbias[base + j + 1];
                o.z = __uint_as_float(dr[j + 2]) + sbias[base + j + 2];
                o.w = __uint_as_float(dr[j + 3]) + sbias[base + j + 3];
                *(float4*)(op + j) = o;
            }
        }
        asm volatile("tcgen05.fence::before_thread_sync;" ::: "memory");
    }
    __syncthreads();
    if (w == 0) {
        asm volatile("tcgen05.dealloc.cta_group::1.sync.aligned.b32 %0, %1;"
                     :: "r"(tmem), "r"(128u));
    }
#else
    // Generic-arch fallback (never executed on sm_103a; keeps compute_103 PTX legal).
    extern __shared__ __align__(1024) char smem[];
    float (*As)[128] = (float(*)[128])smem;
    float (*Bs)[128] = (float(*)[128])(smem + 8192);
    int tid = threadIdx.x;
    int row0 = blockIdx.x << 7;
    int ty = tid >> 4, tx = tid & 15;
    float acc[8][8] = {};
    const float* Hb = H + (size_t)row0 * KDIM;
    for (int kt = 0; kt < KDIM; kt += 16) {
        #pragma unroll
        for (int i = 0; i < 2; i++) {
            int id = tid + i * 256;
            int m = id >> 2, kk = (id & 3) << 2;
            float4 v = *(const float4*)(Hb + (size_t)m * KDIM + kt + kk);
            As[kk + 0][m] = v.x; As[kk + 1][m] = v.y;
            As[kk + 2][m] = v.z; As[kk + 3][m] = v.w;
        }
        #pragma unroll
        for (int i = 0; i < 2; i++) {
            int id = tid + i * 256;
            int k = id >> 5, n4 = (id & 31) << 2;
            *(float4*)&Bs[k][n4] = *(const float4*)(g_A + (kt + k) * CDIM + n4);
        }
        __syncthreads();
        #pragma unroll
        for (int k = 0; k < 16; k++) {
            float a[8], b[8];
            #pragma unroll
            for (int i = 0; i < 8; i++) a[i] = As[k][ty * 8 + i];
            #pragma unroll
            for (int j = 0; j < 8; j++) b[j] = Bs[k][tx * 8 + j];
            #pragma unroll
            for (int i = 0; i < 8; i++)
                #pragma unroll
                for (int j = 0; j < 8; j++) acc[i][j] += a[i] * b[j];
        }
        __syncthreads();
    }
    #pragma unroll
    for (int i = 0; i < 8; i++) {
        size_t r = row0 + ty * 8 + i;
        float* op = g_sim + r * CDIM + tx * 8;
        #pragma unroll
        for (int j = 0; j < 8; j++) op[j] = acc[i][j] + g_bias[tx * 8 + j];
    }
#endif
}

// ================= K2: register-blocked epilogue, 512 threads (R16-proven) =================
#define K2_SMEM 81920
__global__ __launch_bounds__(512) void k2_epi(float* __restrict__ out) {
    extern __shared__ __align__(16) char sm2[];
    float*  snw  = (float*)sm2;
    float2* sLG  = (float2*)(sm2 + 16384);
    int n = blockIdx.x, tid = threadIdx.x;
    int w = tid >> 5, lane = tid & 31;      // w in 0..15
    float* satt = (float*)(sm2 + 32768) + w * (128 * 4);
    float* sfus = (float*)(sm2 + 65536) + w * (64 * 4);

    {
        const float4* src = (const float4*)(g_nw + (size_t)n * 4096);
        float4* dst = (float4*)snw;
        dst[tid] = src[tid];
        dst[tid + 512] = src[tid + 512];
        for (int i = tid; i < 2048; i += 512) sLG[i] = make_float2(g_Lm[i], g_Gm[i]);
    }
    __syncthreads();

    for (int i = 0; i < 4; i++) {
        int b = i * 16 + w;
        size_t row = (size_t)b * N_NODES + n;
        const float* sp = g_sim + row * CDIM;
        float v0 = sp[lane], v1 = sp[lane + 32];
        float v2 = sp[lane + 64], v3 = sp[lane + 96];

        float mx = fmaxf(v0, v1);
        #pragma unroll
        for (int o = 16; o; o >>= 1) mx = fmaxf(mx, __shfl_xor_sync(0xffffffffu, mx, o));
        float e0 = __expf(v0 - mx), e1 = __expf(v1 - mx);
        float s = e0 + e1;
        #pragma unroll
        for (int o = 16; o; o >>= 1) s += __shfl_xor_sync(0xffffffffu, s, o);
        float inv = 1.f / s;

        float mx2 = fmaxf(v2, v3);
        #pragma unroll
        for (int o = 16; o; o >>= 1) mx2 = fmaxf(mx2, __shfl_xor_sync(0xffffffffu, mx2, o));
        float e2 = __expf(v2 - mx2), e3 = __expf(v3 - mx2);
        float s2 = e2 + e3;
        #pragma unroll
        for (int o = 16; o; o >>= 1) s2 += __shfl_xor_sync(0xffffffffu, s2, o);
        float inv2 = 1.f / s2;

        satt[(lane)      * 4 + i] = e0 * inv;
        satt[(lane + 32) * 4 + i] = e1 * inv;
        satt[(lane + 64) * 4 + i] = e2 * inv2;
        satt[(lane + 96) * 4 + i] = e3 * inv2;
    }
    __syncwarp();

    float lctx[4] = {0, 0, 0, 0};
    float gctx[4] = {0, 0, 0, 0};
    #pragma unroll 8
    for (int m = 0; m < 64; m++) {
        float2 lg = sLG[m * 32 + lane];
        float4 al = *(const float4*)&satt[m * 4];
        float4 ag = *(const float4*)&satt[(m + 64) * 4];
        lctx[0] += al.x * lg.x; lctx[1] += al.y * lg.x;
        lctx[2] += al.z * lg.x; lctx[3] += al.w * lg.x;
        gctx[0] += ag.x * lg.y; gctx[1] += ag.y * lg.y;
        gctx[2] += ag.z * lg.y; gctx[3] += ag.w * lg.y;
    }
    #pragma unroll
    for (int r = 0; r < 4; r++) {
        sfus[lane * 4 + r]        = lctx[r];
        sfus[(lane + 32) * 4 + r] = gctx[r];
    }
    __syncwarp();

    const float2* snw2 = (const float2*)snw;
    float2 acc[4];
    #pragma unroll
    for (int r = 0; r < 4; r++) acc[r] = make_float2(0.f, 0.f);
    #pragma unroll 8
    for (int f = 0; f < 64; f++) {
        float2 wv = snw2[f * 32 + lane];
        float4 fr = *(const float4*)&sfus[f * 4];
        acc[0].x += fr.x * wv.x; acc[0].y += fr.x * wv.y;
        acc[1].x += fr.y * wv.x; acc[1].y += fr.y * wv.y;
        acc[2].x += fr.z * wv.x; acc[2].y += fr.z * wv.y;
        acc[3].x += fr.w * wv.x; acc[3].y += fr.w * wv.y;
    }
    #pragma unroll
    for (int r = 0; r < 4; r++) {
        size_t row = (size_t)(r * 16 + w) * N_NODES + n;
        *(float2*)(out + row * HID + 2 * lane) = acc[r];
    }
}

// ================= launch =================
extern "C" void kernel_launch(void* const* d_in, const int* in_sizes, int n_in,
                              void* d_out, int out_size) {
    const float* H    = (const float*)d_in[0];   // [64,1024,12,64]
    const float* G    = (const float*)d_in[1];   // [64,6,32]
    const float* L    = (const float*)d_in[2];   // [64,12,32]
    const float* Wq   = (const float*)d_in[3];   // [64,32]
    const float* bq   = (const float*)d_in[4];   // [32]
    const float* emb  = (const float*)d_in[5];   // [1024,16]
    const float* pool = (const float*)d_in[6];   // [16,64,64]
    float* out = (float*)d_out;                  // [64,1024,64]

    static bool attr_done = false;
    if (!attr_done) {
        cudaFuncSetAttribute(k1_tc, cudaFuncAttributeMaxDynamicSharedMemorySize, K1_SMEM);
        cudaFuncSetAttribute(k2_epi, cudaFuncAttributeMaxDynamicSharedMemorySize, K2_SMEM);
        attr_done = true;
    }

    // k1 in captured launch slot 3.
    pFold_kernel<<<12, 256>>>(G, L, Wq);                 // slot 0
    pAux_kernel <<<9, 256>>>(G, L, bq);                  // slot 1
    pNw_kernel  <<<256, 256>>>(emb, pool);               // slot 2
    k1_tc       <<<ROWS / 128, 256, K1_SMEM>>>(H);       // slot 3  <-- profiled
    k2_epi      <<<N_NODES, 512, K2_SMEM>>>(out);        // slot 4
}